// round 2
// baseline (speedup 1.0000x reference)
#include <cuda_runtime.h>
#include <math.h>

#define W 512
#define H 512
#define BATCH 16
#define NPIX (W*H)
#define NMAP (BATCH*NPIX)
#define EPSF 1e-4f
#define TILE 32

// Static scratch (allocation-free rule): 8 maps x 16MB = 128MB
__device__ float g_buf0[NMAP]; // grayR
__device__ float g_buf1[NMAP]; // grayL
__device__ float g_buf2[NMAP]; // A (pmax1 / m7max)
__device__ float g_buf3[NMAP]; // B (pmin1 / m7min)
__device__ float g_buf4[NMAP]; // C (gmax1)
__device__ float g_buf5[NMAP]; // D (gmin1)
__device__ float g_buf6[NMAP]; // E (go)
__device__ float g_buf7[NMAP]; // S (stored R-direction map)
__device__ double g_acc;

__device__ __forceinline__ float* bufptr(int id) {
    switch (id) {
        case 0: return g_buf0;
        case 1: return g_buf1;
        case 2: return g_buf2;
        case 3: return g_buf3;
        case 4: return g_buf4;
        case 5: return g_buf5;
        case 6: return g_buf6;
        default: return g_buf7;
    }
}

__global__ void k_zero() { g_acc = 0.0; }

// grayscale: 0.299 r + 0.587 g + 0.114 b
__global__ void k_gray(const float* __restrict__ in, int out_id) {
    int i = blockIdx.x * blockDim.x + threadIdx.x;
    if (i >= NMAP) return;
    int b = i / NPIX;
    int p = i - b * NPIX;
    const float* base = in + (size_t)b * 3 * NPIX;
    bufptr(out_id)[i] = 0.299f * base[p] + 0.587f * base[NPIX + p] + 0.114f * base[2 * NPIX + p];
}

// ga = |grad(gray, dir)|; 9x9 valid-window max & min pool (separable, in smem)
__global__ void k_pool9_grad(int gray_id, int omax_id, int omin_id, int dir) {
    const int R = 4, S = TILE + 2 * R; // 40
    __shared__ float sga[S][S + 1];
    __shared__ float shmax[S][TILE];
    __shared__ float shmin[S][TILE];
    int b = blockIdx.z;
    int x0 = blockIdx.x * TILE, y0 = blockIdx.y * TILE;
    int tx = threadIdx.x, ty = threadIdx.y;
    const float* gb = bufptr(gray_id) + (size_t)b * NPIX;

    for (int i = ty; i < S; i += TILE) {
        int gy = y0 - R + i;
        for (int j = tx; j < S; j += TILE) {
            int gx = x0 - R + j;
            float v = 0.f;
            if (gx >= 0 && gx < W && gy >= 0 && gy < H) {
                float c = gb[gy * W + gx];
                float nb = (dir == 0) ? ((gx + 1 < W) ? gb[gy * W + gx + 1] : 0.f)
                                      : ((gy + 1 < H) ? gb[(gy + 1) * W + gx] : 0.f);
                v = fabsf(c - nb);
            }
            sga[i][j] = v;
        }
    }
    __syncthreads();
    // horizontal
    for (int i = ty; i < S; i += TILE) {
        int gx = x0 + tx;
        int lo = max(gx - R, 0) - (x0 - R);
        int hi = min(gx + R, W - 1) - (x0 - R);
        float mx = -3.4e38f, mn = 3.4e38f;
        for (int k = lo; k <= hi; ++k) {
            float v = sga[i][k];
            mx = fmaxf(mx, v);
            mn = fminf(mn, v);
        }
        shmax[i][tx] = mx;
        shmin[i][tx] = mn;
    }
    __syncthreads();
    // vertical
    int gx = x0 + tx, gy = y0 + ty;
    int lo = max(gy - R, 0) - (y0 - R);
    int hi = min(gy + R, H - 1) - (y0 - R);
    float mx = -3.4e38f, mn = 3.4e38f;
    for (int k = lo; k <= hi; ++k) {
        mx = fmaxf(mx, shmax[k][tx]);
        mn = fminf(mn, shmin[k][tx]);
    }
    size_t o = (size_t)b * NPIX + gy * W + gx;
    bufptr(omax_id)[o] = mx;
    bufptr(omin_id)[o] = mn;
}

// dual 17x17 avg pool (count-exclude-pad), separable in smem
__global__ void k_avg17_dual(int in1_id, int in2_id, int out1_id, int out2_id) {
    const int R = 8, S = TILE + 2 * R; // 48
    __shared__ float s1[S][S + 1];
    __shared__ float s2[S][S + 1];
    __shared__ float h1[S][TILE];
    __shared__ float h2[S][TILE];
    int b = blockIdx.z;
    int x0 = blockIdx.x * TILE, y0 = blockIdx.y * TILE;
    int tx = threadIdx.x, ty = threadIdx.y;
    const float* p1 = bufptr(in1_id) + (size_t)b * NPIX;
    const float* p2 = bufptr(in2_id) + (size_t)b * NPIX;

    for (int i = ty; i < S; i += TILE) {
        int gy = y0 - R + i;
        for (int j = tx; j < S; j += TILE) {
            int gx = x0 - R + j;
            float v1 = 0.f, v2 = 0.f;
            if (gx >= 0 && gx < W && gy >= 0 && gy < H) {
                v1 = p1[gy * W + gx];
                v2 = p2[gy * W + gx];
            }
            s1[i][j] = v1;
            s2[i][j] = v2;
        }
    }
    __syncthreads();
    for (int i = ty; i < S; i += TILE) {
        int gx = x0 + tx;
        int lo = max(gx - R, 0) - (x0 - R);
        int hi = min(gx + R, W - 1) - (x0 - R);
        float a = 0.f, c = 0.f;
        for (int k = lo; k <= hi; ++k) { a += s1[i][k]; c += s2[i][k]; }
        h1[i][tx] = a;
        h2[i][tx] = c;
    }
    __syncthreads();
    int gx = x0 + tx, gy = y0 + ty;
    int lo = max(gy - R, 0) - (y0 - R);
    int hi = min(gy + R, H - 1) - (y0 - R);
    float a = 0.f, c = 0.f;
    for (int k = lo; k <= hi; ++k) { a += h1[k][tx]; c += h2[k][tx]; }
    float cntx = (float)(min(gx + R, W - 1) - max(gx - R, 0) + 1);
    float cnty = (float)(min(gy + R, H - 1) - max(gy - R, 0) + 1);
    float inv = 1.f / (cntx * cnty);
    size_t o = (size_t)b * NPIX + gy * W + gx;
    bufptr(out1_id)[o] = a * inv;
    bufptr(out2_id)[o] = c * inv;
}

// go = |avg5(signed grad)|
__global__ void k_avg5_grad(int gray_id, int out_id, int dir) {
    const int R = 2, S = TILE + 2 * R; // 36
    __shared__ float sg[S][S + 1];
    __shared__ float hs[S][TILE];
    int b = blockIdx.z;
    int x0 = blockIdx.x * TILE, y0 = blockIdx.y * TILE;
    int tx = threadIdx.x, ty = threadIdx.y;
    const float* gb = bufptr(gray_id) + (size_t)b * NPIX;

    for (int i = ty; i < S; i += TILE) {
        int gy = y0 - R + i;
        for (int j = tx; j < S; j += TILE) {
            int gx = x0 - R + j;
            float v = 0.f;
            if (gx >= 0 && gx < W && gy >= 0 && gy < H) {
                float c = gb[gy * W + gx];
                float nb = (dir == 0) ? ((gx + 1 < W) ? gb[gy * W + gx + 1] : 0.f)
                                      : ((gy + 1 < H) ? gb[(gy + 1) * W + gx] : 0.f);
                v = c - nb;
            }
            sg[i][j] = v;
        }
    }
    __syncthreads();
    for (int i = ty; i < S; i += TILE) {
        int gx = x0 + tx;
        int lo = max(gx - R, 0) - (x0 - R);
        int hi = min(gx + R, W - 1) - (x0 - R);
        float a = 0.f;
        for (int k = lo; k <= hi; ++k) a += sg[i][k];
        hs[i][tx] = a;
    }
    __syncthreads();
    int gx = x0 + tx, gy = y0 + ty;
    int lo = max(gy - R, 0) - (y0 - R);
    int hi = min(gy + R, H - 1) - (y0 - R);
    float a = 0.f;
    for (int k = lo; k <= hi; ++k) a += hs[k][tx];
    float cntx = (float)(min(gx + R, W - 1) - max(gx - R, 0) + 1);
    float cnty = (float)(min(gy + R, H - 1) - max(gy - R, 0) + 1);
    size_t o = (size_t)b * NPIX + gy * W + gx;
    bufptr(out_id)[o] = fabsf(a / (cntx * cnty));
}

// 7x7 valid-window max & min pool of a plain map
__global__ void k_pool7(int in_id, int omax_id, int omin_id) {
    const int R = 3, S = TILE + 2 * R; // 38
    __shared__ float sv[S][S + 1];
    __shared__ float shmax[S][TILE];
    __shared__ float shmin[S][TILE];
    int b = blockIdx.z;
    int x0 = blockIdx.x * TILE, y0 = blockIdx.y * TILE;
    int tx = threadIdx.x, ty = threadIdx.y;
    const float* p = bufptr(in_id) + (size_t)b * NPIX;

    for (int i = ty; i < S; i += TILE) {
        int gy = y0 - R + i;
        for (int j = tx; j < S; j += TILE) {
            int gx = x0 - R + j;
            float v = 0.f;
            if (gx >= 0 && gx < W && gy >= 0 && gy < H) v = p[gy * W + gx];
            sv[i][j] = v;
        }
    }
    __syncthreads();
    for (int i = ty; i < S; i += TILE) {
        int gx = x0 + tx;
        int lo = max(gx - R, 0) - (x0 - R);
        int hi = min(gx + R, W - 1) - (x0 - R);
        float mx = -3.4e38f, mn = 3.4e38f;
        for (int k = lo; k <= hi; ++k) {
            float v = sv[i][k];
            mx = fmaxf(mx, v);
            mn = fminf(mn, v);
        }
        shmax[i][tx] = mx;
        shmin[i][tx] = mn;
    }
    __syncthreads();
    int gx = x0 + tx, gy = y0 + ty;
    int lo = max(gy - R, 0) - (y0 - R);
    int hi = min(gy + R, H - 1) - (y0 - R);
    float mx = -3.4e38f, mn = 3.4e38f;
    for (int k = lo; k <= hi; ++k) {
        mx = fmaxf(mx, shmax[k][tx]);
        mn = fminf(mn, shmin[k][tx]);
    }
    size_t o = (size_t)b * NPIX + gy * W + gx;
    bufptr(omax_id)[o] = mx;
    bufptr(omin_id)[o] = mn;
}

// final: avg7 of (m7max, m7min) -> pmax, pmin; gn, gn1; out = (gn+0.01)*gn1
// mode 0: store to store_id.  mode 1: read partner (store_id) and accumulate loss term.
__global__ void k_final(int m7max_id, int m7min_id, int gmax1_id, int gmin1_id,
                        int go_id, int gray_id, int dir, int store_id, int mode) {
    const int R = 3, S = TILE + 2 * R; // 38
    __shared__ float s1[S][S + 1];
    __shared__ float s2[S][S + 1];
    __shared__ float h1[S][TILE];
    __shared__ float h2[S][TILE];
    __shared__ double sred[32];
    int b = blockIdx.z;
    int x0 = blockIdx.x * TILE, y0 = blockIdx.y * TILE;
    int tx = threadIdx.x, ty = threadIdx.y;
    const float* p1 = bufptr(m7max_id) + (size_t)b * NPIX;
    const float* p2 = bufptr(m7min_id) + (size_t)b * NPIX;

    for (int i = ty; i < S; i += TILE) {
        int gy = y0 - R + i;
        for (int j = tx; j < S; j += TILE) {
            int gx = x0 - R + j;
            float v1 = 0.f, v2 = 0.f;
            if (gx >= 0 && gx < W && gy >= 0 && gy < H) {
                v1 = p1[gy * W + gx];
                v2 = p2[gy * W + gx];
            }
            s1[i][j] = v1;
            s2[i][j] = v2;
        }
    }
    __syncthreads();
    for (int i = ty; i < S; i += TILE) {
        int gx = x0 + tx;
        int lo = max(gx - R, 0) - (x0 - R);
        int hi = min(gx + R, W - 1) - (x0 - R);
        float a = 0.f, c = 0.f;
        for (int k = lo; k <= hi; ++k) { a += s1[i][k]; c += s2[i][k]; }
        h1[i][tx] = a;
        h2[i][tx] = c;
    }
    __syncthreads();
    int gx = x0 + tx, gy = y0 + ty;
    int lo = max(gy - R, 0) - (y0 - R);
    int hi = min(gy + R, H - 1) - (y0 - R);
    float a = 0.f, c = 0.f;
    for (int k = lo; k <= hi; ++k) { a += h1[k][tx]; c += h2[k][tx]; }
    float cntx = (float)(min(gx + R, W - 1) - max(gx - R, 0) + 1);
    float cnty = (float)(min(gy + R, H - 1) - max(gy - R, 0) + 1);
    float inv = 1.f / (cntx * cnty);
    float pmax = a * inv, pmin = c * inv;

    size_t o = (size_t)b * NPIX + gy * W + gx;
    float gov = bufptr(go_id)[o];
    float gn = (gov - pmin) / (fabsf(pmax - pmin) + EPSF);

    const float* gb = bufptr(gray_id) + (size_t)b * NPIX;
    float cc = gb[gy * W + gx];
    float nb = (dir == 0) ? ((gx + 1 < W) ? gb[gy * W + gx + 1] : 0.f)
                          : ((gy + 1 < H) ? gb[(gy + 1) * W + gx] : 0.f);
    float ga = fabsf(cc - nb);
    float gmaxv = bufptr(gmax1_id)[o];
    float gminv = bufptr(gmin1_id)[o];
    float gn1 = (ga - gminv) / (fabsf(gmaxv - gminv) + EPSF);

    float val = (gn + 0.01f) * gn1;

    if (mode == 0) {
        bufptr(store_id)[o] = val;
    } else {
        float r = bufptr(store_id)[o];
        double term = (double)(r * expf(-10.f * r) * expf(-10.f * val));
        // block reduce into double
        int lane = tx;           // within-warp lane (blockDim.x == 32)
        int warp = ty;           // 32 warps
        double v = term;
        #pragma unroll
        for (int off = 16; off; off >>= 1) v += __shfl_down_sync(0xffffffffu, v, off);
        if (lane == 0) sred[warp] = v;
        __syncthreads();
        if (warp == 0) {
            double w = sred[lane];
            #pragma unroll
            for (int off = 16; off; off >>= 1) w += __shfl_down_sync(0xffffffffu, w, off);
            if (lane == 0) atomicAdd(&g_acc, w);
        }
    }
}

__global__ void k_out(float* __restrict__ out) {
    out[0] = (float)(g_acc / (double)NMAP);
}

extern "C" void kernel_launch(void* const* d_in, const int* in_sizes, int n_in,
                              void* d_out, int out_size) {
    const float* R_low = (const float*)d_in[0];
    const float* low = (const float*)d_in[1];
    float* out = (float*)d_out;

    dim3 tb(TILE, TILE);
    dim3 tg(W / TILE, H / TILE, BATCH);
    int gray_blocks = (NMAP + 255) / 256;

    k_zero<<<1, 1>>>();
    k_gray<<<gray_blocks, 256>>>(R_low, 0);
    k_gray<<<gray_blocks, 256>>>(low, 1);

    for (int dir = 0; dir < 2; ++dir) {
        // R_low combo -> store map in buf 7
        k_pool9_grad<<<tg, tb>>>(0, 2, 3, dir);
        k_avg17_dual<<<tg, tb>>>(2, 3, 4, 5);
        k_avg5_grad<<<tg, tb>>>(0, 6, dir);
        k_pool7<<<tg, tb>>>(6, 2, 3);
        k_final<<<tg, tb>>>(2, 3, 4, 5, 6, 0, dir, 7, 0);
        // low combo -> fuse with stored R map, accumulate
        k_pool9_grad<<<tg, tb>>>(1, 2, 3, dir);
        k_avg17_dual<<<tg, tb>>>(2, 3, 4, 5);
        k_avg5_grad<<<tg, tb>>>(1, 6, dir);
        k_pool7<<<tg, tb>>>(6, 2, 3);
        k_final<<<tg, tb>>>(2, 3, 4, 5, 6, 1, dir, 7, 1);
    }
    k_out<<<1, 1>>>(out);
}

// round 3
// speedup vs baseline: 1.1015x; 1.1015x over previous
#include <cuda_runtime.h>
#include <math.h>

#define W 512
#define H 512
#define BATCH 16
#define NPIX (W*H)
#define NMAP (BATCH*NPIX)
#define EPSF 1e-4f

// Static scratch (allocation-free rule)
__device__ float g_grayR[NMAP];
__device__ float g_grayL[NMAP];
__device__ float g_pmax1[NMAP];
__device__ float g_pmin1[NMAP];
__device__ float g_gmax1[NMAP];
__device__ float g_gmin1[NMAP];
__device__ float g_go[NMAP];
__device__ float g_valR[NMAP];
__device__ float g_ga[NMAP];
__device__ double g_acc;

#define NANF __int_as_float(0x7fffffff)
#define NINF __int_as_float(0xff800000)
#define PINF __int_as_float(0x7f800000)

__global__ void k_zero() { g_acc = 0.0; }

// grayscale, float4-vectorized (planes are contiguous, NPIX % 4 == 0)
__global__ void k_gray(const float* __restrict__ in, float* __restrict__ outp) {
    int i = blockIdx.x * blockDim.x + threadIdx.x;   // vec4 index
    if (i >= NMAP / 4) return;
    int b = i / (NPIX / 4);
    int p = i - b * (NPIX / 4);
    const float4* base = (const float4*)(in + (size_t)b * 3 * NPIX);
    float4 r = base[p];
    float4 g = base[NPIX / 4 + p];
    float4 bl = base[2 * (NPIX / 4) + p];
    float4 o;
    o.x = 0.299f * r.x + 0.587f * g.x + 0.114f * bl.x;
    o.y = 0.299f * r.y + 0.587f * g.y + 0.114f * bl.y;
    o.z = 0.299f * r.z + 0.587f * g.z + 0.114f * bl.z;
    o.w = 0.299f * r.w + 0.587f * g.w + 0.114f * bl.w;
    ((float4*)outp)[i] = o;
}

// ============================================================================
// Kernel A: from gray -> pool9(max,min of |grad|) and go = |avg5(grad)| ; also stores ga
// Block (32,8); output tile 32x32; 4 consecutive rows/thread in vertical passes.
// ============================================================================
template<int DIR>
__global__ __launch_bounds__(256, 4)
void k_pool9_avg5(const float* __restrict__ grayAll) {
    __shared__ float sga[40 * 41];   // |grad|, NaN outside image
    __shared__ float sg0[40 * 41];   // grad,   0 outside image
    __shared__ float hmx[40 * 32];
    __shared__ float hmn[40 * 32];
    __shared__ float hs5[36 * 32];

    int b = blockIdx.z;
    int x0 = blockIdx.x * 32, y0 = blockIdx.y * 32;
    int tx = threadIdx.x, ty = threadIdx.y;
    int tid = ty * 32 + tx;
    const float* gb = grayAll + (size_t)b * NPIX;

    // fill 40x40 region at (x0-4, y0-4)
    for (int idx = tid; idx < 1600; idx += 256) {
        int i = idx / 40, j = idx - i * 40;
        int gy = y0 - 4 + i, gx = x0 - 4 + j;
        float av = NANF, sv = 0.f;
        if (gx >= 0 && gx < W && gy >= 0 && gy < H) {
            float c = gb[gy * W + gx];
            float nb;
            if (DIR == 0) nb = (gx + 1 < W) ? gb[gy * W + gx + 1] : 0.f;
            else          nb = (gy + 1 < H) ? gb[(gy + 1) * W + gx] : 0.f;
            float g = c - nb;
            av = fabsf(g); sv = g;
        }
        sga[i * 41 + j] = av;
        sg0[i * 41 + j] = sv;
    }
    __syncthreads();

    // hpass9: 40 rows x 32 cols, fixed 9 taps (NaN-transparent)
    for (int idx = tid; idx < 1280; idx += 256) {
        int i = idx >> 5, c = idx & 31;
        const float* row = sga + i * 41 + c;
        float mx = NINF, mn = PINF;
        #pragma unroll
        for (int k = 0; k < 9; k++) { float v = row[k]; mx = fmaxf(mx, v); mn = fminf(mn, v); }
        hmx[i * 32 + c] = mx;
        hmn[i * 32 + c] = mn;
    }
    // hpass5: 36 rows x 32 cols, fixed 5-tap sum (0 outside)
    for (int idx = tid; idx < 1152; idx += 256) {
        int i5 = idx >> 5, c = idx & 31;
        const float* row = sg0 + (i5 + 2) * 41 + c + 2;
        float s = 0.f;
        #pragma unroll
        for (int k = 0; k < 5; k++) s += row[k];
        hs5[i5 * 32 + c] = s;
    }
    __syncthreads();

    int yb = ty * 4;
    size_t base = (size_t)b * NPIX + (size_t)(y0 + yb) * W + x0 + tx;

    // vpass9: 4 outputs/thread with shared 6-tap core
    {
        float t9x[12], t9n[12];
        #pragma unroll
        for (int q = 0; q < 12; q++) {
            t9x[q] = hmx[(yb + q) * 32 + tx];
            t9n[q] = hmn[(yb + q) * 32 + tx];
        }
        float cx = t9x[3], cn = t9n[3];
        #pragma unroll
        for (int q = 4; q <= 8; q++) { cx = fmaxf(cx, t9x[q]); cn = fminf(cn, t9n[q]); }
        float ox0 = fmaxf(fmaxf(fmaxf(cx, t9x[0]), t9x[1]), t9x[2]);
        float ox1 = fmaxf(fmaxf(fmaxf(cx, t9x[1]), t9x[2]), t9x[9]);
        float ox2 = fmaxf(fmaxf(fmaxf(cx, t9x[2]), t9x[9]), t9x[10]);
        float ox3 = fmaxf(fmaxf(fmaxf(cx, t9x[9]), t9x[10]), t9x[11]);
        float on0 = fminf(fminf(fminf(cn, t9n[0]), t9n[1]), t9n[2]);
        float on1 = fminf(fminf(fminf(cn, t9n[1]), t9n[2]), t9n[9]);
        float on2 = fminf(fminf(fminf(cn, t9n[2]), t9n[9]), t9n[10]);
        float on3 = fminf(fminf(fminf(cn, t9n[9]), t9n[10]), t9n[11]);
        g_pmax1[base + 0 * W] = ox0; g_pmin1[base + 0 * W] = on0;
        g_pmax1[base + 1 * W] = ox1; g_pmin1[base + 1 * W] = on1;
        g_pmax1[base + 2 * W] = ox2; g_pmin1[base + 2 * W] = on2;
        g_pmax1[base + 3 * W] = ox3; g_pmin1[base + 3 * W] = on3;
        #pragma unroll
        for (int r = 0; r < 4; r++)
            g_ga[base + r * W] = sga[(yb + r + 4) * 41 + tx + 4];
    }
    // vpass5: sliding sums -> go
    {
        float t[8];
        #pragma unroll
        for (int q = 0; q < 8; q++) t[q] = hs5[(yb + q) * 32 + tx];
        float s0 = t[0] + t[1] + t[2] + t[3] + t[4];
        float s1 = s0 - t[0] + t[5];
        float s2 = s1 - t[1] + t[6];
        float s3 = s2 - t[2] + t[7];
        float ss[4] = { s0, s1, s2, s3 };
        int gx = x0 + tx;
        float cntx = (float)(min(gx + 2, W - 1) - max(gx - 2, 0) + 1);
        #pragma unroll
        for (int r = 0; r < 4; r++) {
            int gy = y0 + yb + r;
            float cnty = (float)(min(gy + 2, H - 1) - max(gy - 2, 0) + 1);
            g_go[base + r * W] = fabsf(__fdividef(ss[r], cntx * cnty));
        }
    }
}

// ============================================================================
// Kernel B: dual 17x17 avg (count-exclude-pad) of pmax1/pmin1 -> gmax1/gmin1
// ============================================================================
__global__ __launch_bounds__(256, 4)
void k_avg17() {
    __shared__ float s1[48 * 49];
    __shared__ float s2[48 * 49];
    __shared__ float h1[48 * 32];
    __shared__ float h2[48 * 32];

    int b = blockIdx.z;
    int x0 = blockIdx.x * 32, y0 = blockIdx.y * 32;
    int tx = threadIdx.x, ty = threadIdx.y;
    int tid = ty * 32 + tx;
    const float* p1 = g_pmax1 + (size_t)b * NPIX;
    const float* p2 = g_pmin1 + (size_t)b * NPIX;

    for (int idx = tid; idx < 2304; idx += 256) {
        int i = idx / 48, j = idx - i * 48;
        int gy = y0 - 8 + i, gx = x0 - 8 + j;
        float v1 = 0.f, v2 = 0.f;
        if (gx >= 0 && gx < W && gy >= 0 && gy < H) {
            v1 = p1[gy * W + gx];
            v2 = p2[gy * W + gx];
        }
        s1[i * 49 + j] = v1;
        s2[i * 49 + j] = v2;
    }
    __syncthreads();

    // hpass: 48 rows x 32 cols, 17 taps
    for (int idx = tid; idx < 1536; idx += 256) {
        int i = idx >> 5, c = idx & 31;
        const float* r1 = s1 + i * 49 + c;
        const float* r2 = s2 + i * 49 + c;
        float a = 0.f, d = 0.f;
        #pragma unroll
        for (int k = 0; k < 17; k++) { a += r1[k]; d += r2[k]; }
        h1[i * 32 + c] = a;
        h2[i * 32 + c] = d;
    }
    __syncthreads();

    // vpass: sliding 17-window, 4 outputs/thread
    int yb = ty * 4;
    float a0 = 0.f, d0 = 0.f;
    float sa0, sa1, sa2, sd0, sd1, sd2;
    #pragma unroll
    for (int q = 0; q < 17; q++) {
        float va = h1[(yb + q) * 32 + tx];
        float vd = h2[(yb + q) * 32 + tx];
        a0 += va; d0 += vd;
        if (q == 0) { sa0 = va; sd0 = vd; }
        if (q == 1) { sa1 = va; sd1 = vd; }
        if (q == 2) { sa2 = va; sd2 = vd; }
    }
    float ea0 = h1[(yb + 17) * 32 + tx], ed0 = h2[(yb + 17) * 32 + tx];
    float ea1 = h1[(yb + 18) * 32 + tx], ed1 = h2[(yb + 18) * 32 + tx];
    float ea2 = h1[(yb + 19) * 32 + tx], ed2 = h2[(yb + 19) * 32 + tx];
    float a1 = a0 - sa0 + ea0, d1 = d0 - sd0 + ed0;
    float a2 = a1 - sa1 + ea1, d2 = d1 - sd1 + ed1;
    float a3 = a2 - sa2 + ea2, d3 = d2 - sd2 + ed2;
    float aa[4] = { a0, a1, a2, a3 };
    float dd[4] = { d0, d1, d2, d3 };

    int gx = x0 + tx;
    float cntx = (float)(min(gx + 8, W - 1) - max(gx - 8, 0) + 1);
    size_t base = (size_t)b * NPIX + (size_t)(y0 + yb) * W + gx;
    #pragma unroll
    for (int r = 0; r < 4; r++) {
        int gy = y0 + yb + r;
        float cnty = (float)(min(gy + 8, H - 1) - max(gy - 8, 0) + 1);
        float inv = __fdividef(1.f, cntx * cnty);
        g_gmax1[base + r * W] = aa[r] * inv;
        g_gmin1[base + r * W] = dd[r] * inv;
    }
}

// ============================================================================
// Kernel C: pool7(max,min) of go + avg7 of both + final normalize / combine
// mode 0: store val map; mode 1: read partner map, accumulate loss
// ============================================================================
__global__ __launch_bounds__(256, 4)
void k_final7(int mode) {
    __shared__ float sgo[44 * 45];      // go, NaN outside
    __shared__ float sA[44 * 38];       // hm7max, later avg7 hsum (38*32)
    __shared__ float sB[44 * 38];       // hm7min, later avg7 hsum
    __shared__ float m7x[38 * 39];
    __shared__ float m7n[38 * 39];
    __shared__ double sred[8];

    int b = blockIdx.z;
    int x0 = blockIdx.x * 32, y0 = blockIdx.y * 32;
    int tx = threadIdx.x, ty = threadIdx.y;
    int tid = ty * 32 + tx;
    const float* pgo = g_go + (size_t)b * NPIX;

    // fill go with halo 6 (NaN outside image)
    for (int idx = tid; idx < 1936; idx += 256) {
        int i = idx / 44, j = idx - i * 44;
        int gy = y0 - 6 + i, gx = x0 - 6 + j;
        float v = NANF;
        if (gx >= 0 && gx < W && gy >= 0 && gy < H) v = pgo[gy * W + gx];
        sgo[i * 45 + j] = v;
    }
    __syncthreads();

    // hpass7: 44 rows x 38 cols (x in [-3,34])
    for (int idx = tid; idx < 1672; idx += 256) {
        int i = idx / 38, c = idx - i * 38;
        const float* row = sgo + i * 45 + c;
        float mx = NINF, mn = PINF;
        #pragma unroll
        for (int k = 0; k < 7; k++) { float v = row[k]; mx = fmaxf(mx, v); mn = fminf(mn, v); }
        sA[i * 38 + c] = mx;
        sB[i * 38 + c] = mn;
    }
    __syncthreads();

    // vpass7 + mask to 0 outside image -> m7x/m7n on 38x38 region
    for (int idx = tid; idx < 1444; idx += 256) {
        int ro = idx / 38, c = idx - ro * 38;
        float mx = NINF, mn = PINF;
        #pragma unroll
        for (int k = 0; k < 7; k++) {
            mx = fmaxf(mx, sA[(ro + k) * 38 + c]);
            mn = fminf(mn, sB[(ro + k) * 38 + c]);
        }
        int gx = x0 + c - 3, gy = y0 + ro - 3;
        bool inside = (gx >= 0 && gx < W && gy >= 0 && gy < H);
        m7x[ro * 39 + c] = inside ? mx : 0.f;
        m7n[ro * 39 + c] = inside ? mn : 0.f;
    }
    __syncthreads();

    // avg7 hpass: 38 rows x 32 cols (reuse sA/sB as [38*32])
    for (int idx = tid; idx < 1216; idx += 256) {
        int i = idx >> 5, c = idx & 31;
        float a = 0.f, d = 0.f;
        #pragma unroll
        for (int k = 0; k < 7; k++) {
            a += m7x[i * 39 + c + k];
            d += m7n[i * 39 + c + k];
        }
        sA[i * 32 + c] = a;
        sB[i * 32 + c] = d;
    }
    __syncthreads();

    // avg7 vpass (sliding) + final math, 4 outputs/thread
    int yb = ty * 4;
    float ta[10], tb[10];
    #pragma unroll
    for (int q = 0; q < 10; q++) {
        ta[q] = sA[(yb + q) * 32 + tx];
        tb[q] = sB[(yb + q) * 32 + tx];
    }
    float a0 = ta[0] + ta[1] + ta[2] + ta[3] + ta[4] + ta[5] + ta[6];
    float a1 = a0 - ta[0] + ta[7];
    float a2 = a1 - ta[1] + ta[8];
    float a3 = a2 - ta[2] + ta[9];
    float d0 = tb[0] + tb[1] + tb[2] + tb[3] + tb[4] + tb[5] + tb[6];
    float d1 = d0 - tb[0] + tb[7];
    float d2 = d1 - tb[1] + tb[8];
    float d3 = d2 - tb[2] + tb[9];
    float aa[4] = { a0, a1, a2, a3 };
    float dd[4] = { d0, d1, d2, d3 };

    int gx = x0 + tx;
    float cntx = (float)(min(gx + 3, W - 1) - max(gx - 3, 0) + 1);
    size_t base = (size_t)b * NPIX + (size_t)(y0 + yb) * W + gx;

    double acc = 0.0;
    #pragma unroll
    for (int r = 0; r < 4; r++) {
        int gy = y0 + yb + r;
        float cnty = (float)(min(gy + 3, H - 1) - max(gy - 3, 0) + 1);
        float inv = __fdividef(1.f, cntx * cnty);
        float pmax = aa[r] * inv, pmin = dd[r] * inv;
        size_t o = base + (size_t)r * W;
        float go = sgo[(yb + r + 6) * 45 + tx + 6];
        float gn = __fdividef(go - pmin, fabsf(pmax - pmin) + EPSF);
        float ga = g_ga[o];
        float gmx = g_gmax1[o], gmn = g_gmin1[o];
        float gn1 = __fdividef(ga - gmn, fabsf(gmx - gmn) + EPSF);
        float val = (gn + 0.01f) * gn1;
        if (mode == 0) {
            g_valR[o] = val;
        } else {
            float rv = g_valR[o];
            acc += (double)(rv * expf(-10.f * (rv + val)));
        }
    }

    if (mode == 1) {
        // block reduce (8 warps)
        #pragma unroll
        for (int off = 16; off; off >>= 1) acc += __shfl_down_sync(0xffffffffu, acc, off);
        if (tx == 0) sred[ty] = acc;
        __syncthreads();
        if (tid < 8) {
            double w = sred[tid];
            #pragma unroll
            for (int off = 4; off; off >>= 1) w += __shfl_down_sync(0xffu, w, off);
            if (tid == 0) atomicAdd(&g_acc, w);
        }
    }
}

__global__ void k_out(float* __restrict__ out) {
    out[0] = (float)(g_acc / (double)NMAP);
}

extern "C" void kernel_launch(void* const* d_in, const int* in_sizes, int n_in,
                              void* d_out, int out_size) {
    const float* R_low = (const float*)d_in[0];
    const float* low = (const float*)d_in[1];
    float* out = (float*)d_out;

    dim3 blk(32, 8);
    dim3 grd(16, 16, 16);
    int gray_blocks = (NMAP / 4 + 255) / 256;

    k_zero<<<1, 1>>>();
    k_gray<<<gray_blocks, 256>>>(R_low, g_grayR);
    k_gray<<<gray_blocks, 256>>>(low, g_grayL);

    // dir 0 (x)
    k_pool9_avg5<0><<<grd, blk>>>(g_grayR);
    k_avg17<<<grd, blk>>>();
    k_final7<<<grd, blk>>>(0);
    k_pool9_avg5<0><<<grd, blk>>>(g_grayL);
    k_avg17<<<grd, blk>>>();
    k_final7<<<grd, blk>>>(1);
    // dir 1 (y)
    k_pool9_avg5<1><<<grd, blk>>>(g_grayR);
    k_avg17<<<grd, blk>>>();
    k_final7<<<grd, blk>>>(0);
    k_pool9_avg5<1><<<grd, blk>>>(g_grayL);
    k_avg17<<<grd, blk>>>();
    k_final7<<<grd, blk>>>(1);

    k_out<<<1, 1>>>(out);
}

// round 5
// speedup vs baseline: 1.9669x; 1.7857x over previous
#include <cuda_runtime.h>
#include <math.h>

#define W 512
#define H 512
#define BATCH 16
#define NPIX (W*H)
#define NMAP (BATCH*NPIX)
#define EPSF 1e-4f

#define NANF __int_as_float(0x7fffffff)
#define NINF __int_as_float(0xff800000)
#define PINF __int_as_float(0x7f800000)

// gray maps for both images: [img][batch][H][W]
__device__ float g_gray[2 * NMAP];
__device__ double g_acc;

// ---------------- smem layout (floats) ----------------
#define OFF_GRAY 0
#define OFF_SGA  3422
#define OFF_GO   6614
#define OFF_A    8594
#define OFF_B    13106
#define OFF_C    18482
#define SMEM_FLOATS 23186
#define SMEM_BYTES (SMEM_FLOATS * 4)

__global__ void k_zero() { g_acc = 0.0; }

// grayscale, float4 vectorized
__global__ void k_gray(const float* __restrict__ in, float* __restrict__ outp) {
    int i = blockIdx.x * blockDim.x + threadIdx.x;
    if (i >= NMAP / 4) return;
    int b = i / (NPIX / 4);
    int p = i - b * (NPIX / 4);
    const float4* base = (const float4*)(in + (size_t)b * 3 * NPIX);
    float4 r = base[p];
    float4 g = base[NPIX / 4 + p];
    float4 bl = base[2 * (NPIX / 4) + p];
    float4 o;
    o.x = 0.299f * r.x + 0.587f * g.x + 0.114f * bl.x;
    o.y = 0.299f * r.y + 0.587f * g.y + 0.114f * bl.y;
    o.z = 0.299f * r.z + 0.587f * g.z + 0.114f * bl.z;
    o.w = 0.299f * r.w + 0.587f * g.w + 0.114f * bl.w;
    ((float4*)outp)[i] = o;
}

__global__ __launch_bounds__(1024)
void k_mega(float* __restrict__ out_unused) {
    extern __shared__ float S[];
    __shared__ double sred[32];

    const int b = blockIdx.z;
    const int X0 = blockIdx.x * 32, Y0 = blockIdx.y * 32;
    const int tid = threadIdx.x;
    const int tx = tid & 31, ty = tid >> 5;

    double acc = 0.0;
    float vsave[2];

    #pragma unroll
    for (int img = 0; img < 2; ++img) {
        const float* __restrict__ gp = g_gray + (size_t)img * NMAP + (size_t)b * NPIX;

        __syncthreads();  // protect previous iteration's reads
        // ---- load gray tile 58x58 at (-12,-12), 0 outside image ----
        #pragma unroll
        for (int u = 0; u < 4; ++u) {
            int idx = tid + u * 1024;
            if (idx < 3364) {
                int r = idx / 58, c = idx - r * 58;
                int gy = Y0 - 12 + r, gx = X0 - 12 + c;
                float v = 0.f;
                if ((unsigned)gx < (unsigned)W && (unsigned)gy < (unsigned)H)
                    v = __ldg(gp + gy * W + gx);
                S[OFF_GRAY + r * 59 + c] = v;
            }
        }
        __syncthreads();

        #pragma unroll
        for (int dir = 0; dir < 2; ++dir) {
            // ---- P1: sga (56x56 @ -12, NaN outside), sg0 (48x48 @ -8, 0 outside) ----
            #pragma unroll
            for (int u = 0; u < 4; ++u) {
                int idx = tid + u * 1024;
                if (idx < 3136) {
                    int r = idx / 56, c = idx - r * 56;
                    int gy = Y0 - 12 + r, gx = X0 - 12 + c;
                    float cc = S[OFF_GRAY + r * 59 + c];
                    float nb = (dir == 0) ? S[OFF_GRAY + r * 59 + c + 1]
                                          : S[OFF_GRAY + (r + 1) * 59 + c];
                    bool inside = ((unsigned)gx < (unsigned)W) && ((unsigned)gy < (unsigned)H);
                    S[OFF_SGA + r * 57 + c] = inside ? fabsf(cc - nb) : NANF;
                }
            }
            #pragma unroll
            for (int u = 0; u < 3; ++u) {
                int idx = tid + u * 1024;
                if (idx < 2304) {
                    int r = idx / 48, c = idx - r * 48;
                    int gy = Y0 - 8 + r, gx = X0 - 8 + c;
                    float cc = S[OFF_GRAY + (r + 4) * 59 + (c + 4)];
                    float nb = (dir == 0) ? S[OFF_GRAY + (r + 4) * 59 + (c + 5)]
                                          : S[OFF_GRAY + (r + 5) * 59 + (c + 4)];
                    bool inside = ((unsigned)gx < (unsigned)W) && ((unsigned)gy < (unsigned)H);
                    S[OFF_A + r * 49 + c] = inside ? (cc - nb) : 0.f;
                }
            }
            __syncthreads();

            // ---- P2: hmx/hmn (56 rows x 48 cols), hs5 (48 x 44) ----
            #pragma unroll
            for (int u = 0; u < 3; ++u) {
                int idx = tid + u * 1024;
                if (idx < 2688) {
                    int r = idx / 48, c = idx - r * 48;
                    const float* row = S + OFF_SGA + r * 57 + c;
                    float mx = NINF, mn = PINF;
                    #pragma unroll
                    for (int k = 0; k < 9; ++k) { float v = row[k]; mx = fmaxf(mx, v); mn = fminf(mn, v); }
                    S[OFF_B + r * 48 + c] = mx;
                    S[OFF_B + 2688 + r * 48 + c] = mn;
                }
            }
            #pragma unroll
            for (int u = 0; u < 3; ++u) {
                int idx = tid + u * 1024;
                if (idx < 2112) {
                    int r = idx / 44, c = idx - r * 44;
                    const float* row = S + OFF_A + r * 49 + c;
                    float s = row[0] + row[1] + row[2] + row[3] + row[4];
                    S[OFF_A + 2352 + r * 45 + c] = s;
                }
            }
            __syncthreads();

            // ---- P3: pmx/pmn (48x48 @ -8, MASKED to 0 outside image), go (44x44 @ -6) ----
            #pragma unroll
            for (int u = 0; u < 3; ++u) {
                int idx = tid + u * 1024;
                if (idx < 2304) {
                    int r = idx / 48, c = idx - r * 48;
                    float mx = NINF, mn = PINF;
                    #pragma unroll
                    for (int k = 0; k < 9; ++k) {
                        mx = fmaxf(mx, S[OFF_B + (r + k) * 48 + c]);
                        mn = fminf(mn, S[OFF_B + 2688 + (r + k) * 48 + c]);
                    }
                    int gy = Y0 - 8 + r, gx = X0 - 8 + c;
                    bool inside = ((unsigned)gx < (unsigned)W) && ((unsigned)gy < (unsigned)H);
                    // outside positions must contribute 0 to the avg17 sum
                    S[OFF_C + r * 49 + c] = inside ? mx : 0.f;
                    S[OFF_C + 2352 + r * 49 + c] = inside ? mn : 0.f;
                }
            }
            #pragma unroll
            for (int u = 0; u < 2; ++u) {
                int idx = tid + u * 1024;
                if (idx < 1936) {
                    int r = idx / 44, c = idx - r * 44;
                    float s = 0.f;
                    #pragma unroll
                    for (int k = 0; k < 5; ++k) s += S[OFF_A + 2352 + (r + k) * 45 + c];
                    int gy = Y0 - 6 + r, gx = X0 - 6 + c;
                    float v = NANF;
                    if ((unsigned)gx < (unsigned)W && (unsigned)gy < (unsigned)H) {
                        float cntx = (float)(min(gx + 2, W - 1) - max(gx - 2, 0) + 1);
                        float cnty = (float)(min(gy + 2, H - 1) - max(gy - 2, 0) + 1);
                        v = fabsf(__fdividef(s, cntx * cnty));
                    }
                    S[OFF_GO + r * 45 + c] = v;
                }
            }
            __syncthreads();

            // ---- P4: h17 (48x32) from pm; h7x/h7n (44x38) from go ----
            #pragma unroll
            for (int u = 0; u < 2; ++u) {
                int idx = tid + u * 1024;
                if (idx < 1536) {
                    int r = idx >> 5, c = idx & 31;
                    float a = 0.f, d = 0.f;
                    #pragma unroll
                    for (int k = 0; k < 17; ++k) {
                        a += S[OFF_C + r * 49 + c + k];
                        d += S[OFF_C + 2352 + r * 49 + c + k];
                    }
                    S[OFF_B + r * 32 + c] = a;
                    S[OFF_B + 1536 + r * 32 + c] = d;
                }
            }
            #pragma unroll
            for (int u = 0; u < 2; ++u) {
                int idx = tid + u * 1024;
                if (idx < 1672) {
                    int r = idx / 38, c = idx - r * 38;
                    float mx = NINF, mn = PINF;
                    #pragma unroll
                    for (int k = 0; k < 7; ++k) {
                        float v = S[OFF_GO + r * 45 + c + k];
                        mx = fmaxf(mx, v); mn = fminf(mn, v);
                    }
                    S[OFF_A + r * 39 + c] = mx;
                    S[OFF_A + 1716 + r * 39 + c] = mn;
                }
            }
            __syncthreads();

            // ---- P5: m7 (38x38 @ -3, masked 0 outside); v17 per-thread ----
            #pragma unroll
            for (int u = 0; u < 2; ++u) {
                int idx = tid + u * 1024;
                if (idx < 1444) {
                    int r = idx / 38, c = idx - r * 38;
                    float mx = NINF, mn = PINF;
                    #pragma unroll
                    for (int k = 0; k < 7; ++k) {
                        mx = fmaxf(mx, S[OFF_A + (r + k) * 39 + c]);
                        mn = fminf(mn, S[OFF_A + 1716 + (r + k) * 39 + c]);
                    }
                    int gy = Y0 - 3 + r, gx = X0 - 3 + c;
                    bool inside = ((unsigned)gx < (unsigned)W) && ((unsigned)gy < (unsigned)H);
                    S[OFF_C + r * 39 + c] = inside ? mx : 0.f;
                    S[OFF_C + 1482 + r * 39 + c] = inside ? mn : 0.f;
                }
            }
            float gmax, gmin;
            {
                float a = 0.f, d = 0.f;
                #pragma unroll
                for (int k = 0; k < 17; ++k) {
                    a += S[OFF_B + (ty + k) * 32 + tx];
                    d += S[OFF_B + 1536 + (ty + k) * 32 + tx];
                }
                int gx = X0 + tx, gy = Y0 + ty;
                float cntx = (float)(min(gx + 8, W - 1) - max(gx - 8, 0) + 1);
                float cnty = (float)(min(gy + 8, H - 1) - max(gy - 8, 0) + 1);
                float inv = __fdividef(1.f, cntx * cnty);
                gmax = a * inv; gmin = d * inv;
            }
            __syncthreads();

            // ---- P6: h7s (38x32) from m7 ----
            #pragma unroll
            for (int u = 0; u < 2; ++u) {
                int idx = tid + u * 1024;
                if (idx < 1216) {
                    int r = idx >> 5, c = idx & 31;
                    float a = 0.f, d = 0.f;
                    #pragma unroll
                    for (int k = 0; k < 7; ++k) {
                        a += S[OFF_C + r * 39 + c + k];
                        d += S[OFF_C + 1482 + r * 39 + c + k];
                    }
                    S[OFF_A + r * 32 + c] = a;
                    S[OFF_A + 1216 + r * 32 + c] = d;
                }
            }
            __syncthreads();

            // ---- P7: per-thread final ----
            {
                float a = 0.f, d = 0.f;
                #pragma unroll
                for (int k = 0; k < 7; ++k) {
                    a += S[OFF_A + (ty + k) * 32 + tx];
                    d += S[OFF_A + 1216 + (ty + k) * 32 + tx];
                }
                int gx = X0 + tx, gy = Y0 + ty;
                float cntx = (float)(min(gx + 3, W - 1) - max(gx - 3, 0) + 1);
                float cnty = (float)(min(gy + 3, H - 1) - max(gy - 3, 0) + 1);
                float inv = __fdividef(1.f, cntx * cnty);
                float pmax = a * inv, pmin = d * inv;
                float go = S[OFF_GO + (ty + 6) * 45 + tx + 6];
                float ga = S[OFF_SGA + (ty + 12) * 57 + tx + 12];
                float gn = __fdividef(go - pmin, fabsf(pmax - pmin) + EPSF);
                float gn1 = __fdividef(ga - gmin, fabsf(gmax - gmin) + EPSF);
                float val = (gn + 0.01f) * gn1;
                if (img == 0) {
                    vsave[dir] = val;
                } else {
                    float rv = vsave[dir];
                    acc += (double)(rv * expf(-10.f * (rv + val)));
                }
            }
            __syncthreads();  // before next dir overwrites buffers
        }
    }

    // ---- block reduction ----
    #pragma unroll
    for (int off = 16; off; off >>= 1) acc += __shfl_down_sync(0xffffffffu, acc, off);
    if (tx == 0) sred[ty] = acc;
    __syncthreads();
    if (ty == 0) {
        double w = sred[tx];
        #pragma unroll
        for (int off = 16; off; off >>= 1) w += __shfl_down_sync(0xffffffffu, w, off);
        if (tx == 0) atomicAdd(&g_acc, w);
    }
}

__global__ void k_out(float* __restrict__ out) {
    out[0] = (float)(g_acc / (double)NMAP);
}

extern "C" void kernel_launch(void* const* d_in, const int* in_sizes, int n_in,
                              void* d_out, int out_size) {
    const float* R_low = (const float*)d_in[0];
    const float* low = (const float*)d_in[1];
    float* out = (float*)d_out;

    cudaFuncSetAttribute(k_mega, cudaFuncAttributeMaxDynamicSharedMemorySize, SMEM_BYTES);

    float* grayR;
    float* grayL;
    cudaGetSymbolAddress((void**)&grayR, g_gray);
    grayL = grayR + NMAP;

    int gray_blocks = (NMAP / 4 + 255) / 256;

    k_zero<<<1, 1>>>();
    k_gray<<<gray_blocks, 256>>>(R_low, grayR);
    k_gray<<<gray_blocks, 256>>>(low, grayL);

    dim3 grd(16, 16, 16);
    k_mega<<<grd, 1024, SMEM_BYTES>>>(out);

    k_out<<<1, 1>>>(out);
}